// round 14
// baseline (speedup 1.0000x reference)
#include <cuda_runtime.h>
#include <cuda_fp16.h>
#include <cstdint>
#include <cstddef>

// NeRD pixel decoder, fully fused per image row — fp16 mma.sync m16n8k16,
// ldmatrix.x4, cp.async, K=64 slabs, 2-deep kk fragment pipeline, and
// strength-reduced addressing (R13): all LDSM/staging addresses are
// base + small-immediate; no div/mod/IMAD chains in the hot loop.
// Weights pre-scaled by 2^8 (exact); epilogue multiplies acc by 2^-8.
//
//   Layer 0: [128 x 3200] @ [3200 x 256] as 50 K=64 slabs (25 taps x 2 ch)
//   Layers 1,2: [128 x 256] @ [256 x 256] as 4 K=64 slabs each
//   Head: [128 x 256] @ [256 x 3] scalar
// One CTA = one (batch, image-row). 8 warps, warp tile 64x64, acc fp32.

#define FC   128
#define HID  256
#define OUTC 3
#define IMH  128
#define IMW  128
#define OMEGA 30.0f
#define THREADS 256
#define WSCALE 256.0f
#define INV_WSCALE 0.00390625f

#define SMH_H 264
#define SMA_H 72
#define SMB_H 72
#define SMH_HALF (128 * SMH_H)      // 33792
#define SMA_HALF (132 * SMA_H)      // 9504 (x2 alias into smH)
#define SMB_HALF (256 * SMB_H)      // 18432
#define OFF_B(st) (SMH_HALF + (st) * SMB_HALF)
#define SMEM_BYTES ((SMH_HALF + 3 * SMB_HALF) * 2)   // 178176 B

__device__ __half g_xiA[2 * 2 * 132 * 132 * 64];   // [((b*2+ch)*132+hp)][wa*64+kc]
__device__ __half g_W0s[25 * 2 * 256 * 64];        // [(tap*2+ch)*256+n][kc] *2^8
__device__ __half g_W1s[4 * 256 * 64];             // [(kb*256+n)][kc]      *2^8
__device__ __half g_W2s[4 * 256 * 64];

__device__ __forceinline__ void mma16(float* c, const unsigned* a, unsigned b0, unsigned b1) {
    asm("mma.sync.aligned.m16n8k16.row.col.f32.f16.f16.f32 "
        "{%0,%1,%2,%3}, {%4,%5,%6,%7}, {%8,%9}, {%0,%1,%2,%3};"
        : "+f"(c[0]), "+f"(c[1]), "+f"(c[2]), "+f"(c[3])
        : "r"(a[0]), "r"(a[1]), "r"(a[2]), "r"(a[3]), "r"(b0), "r"(b1));
}

__device__ __forceinline__ void ldsm4(unsigned& r0, unsigned& r1, unsigned& r2,
                                      unsigned& r3, unsigned addr) {
    asm volatile("ldmatrix.sync.aligned.m8n8.x4.shared.b16 {%0,%1,%2,%3}, [%4];"
                 : "=r"(r0), "=r"(r1), "=r"(r2), "=r"(r3) : "r"(addr));
}

__device__ __forceinline__ void cpa16(unsigned dst, const void* src) {
    asm volatile("cp.async.ca.shared.global [%0], [%1], 16;" :: "r"(dst), "l"(src));
}
#define CP_COMMIT asm volatile("cp.async.commit_group;" ::: "memory")
#define CP_WAIT(n) asm volatile("cp.async.wait_group %0;" :: "n"(n) : "memory")

// ================= fused prep kernel (unchanged from R12) =================
#define XI_BLOCKS 528
extern "C" __global__ void prep_kernel(const float* __restrict__ xi,
                                       const float* __restrict__ W0,
                                       const float* __restrict__ W1,
                                       const float* __restrict__ W2) {
    const int tid = threadIdx.x;
    if (blockIdx.x < XI_BLOCKS) {
        __shared__ __half smT[64][134];
        const int bi = blockIdx.x;
        const int hp = bi % 132;
        const int t  = bi / 132;
        const int ch = t & 1, b = t >> 1;
        const int h  = hp - 2;
        const bool hok = (unsigned)h < IMH;
        if (tid < 64) {
            smT[tid][0] = __half(0); smT[tid][1] = __half(0);
            smT[tid][130] = __half(0); smT[tid][131] = __half(0);
        }
        const int w = tid & 127, cl0 = tid >> 7;
        for (int cc = 0; cc < 64; cc += 2) {
            const int cl = cc + cl0;
            float v = 0.f;
            if (hok)
                v = xi[(((size_t)b * FC + ch * 64 + cl) * IMH + h) * IMW + w];
            smT[cl][w + 2] = __float2half_rn(v);
        }
        __syncthreads();
        __half2* dst2 = (__half2*)(g_xiA + ((size_t)bi) * (132 * 64));
        for (int r2 = tid; r2 < 132 * 32; r2 += THREADS) {
            const int kc2 = r2 & 31, wa = r2 >> 5;
            dst2[r2] = __halves2half2(smT[2 * kc2][wa], smT[2 * kc2 + 1][wa]);
        }
    } else {
        const int base = (blockIdx.x - XI_BLOCKS) * 2048;
        const int NW0 = 25 * 2 * 256 * 64;
#pragma unroll
        for (int l = 0; l < 8; ++l) {
            const int idx = base + l * 256 + tid;
            if (idx < NW0) {
                const int kc = idx & 63, n = (idx >> 6) & 255;
                const int ch = (idx >> 14) & 1, tap = idx >> 15;
                const int c = ch * 64 + kc;
                g_W0s[idx] = __float2half_rn(W0[((size_t)c * 25 + tap) * HID + n] * WSCALE);
            } else {
                int r = idx - NW0;
                if (r < 2 * 65536) {
                    const int which = r >> 16; r &= 65535;
                    const int kc = r & 63, n = (r >> 6) & 255, kb = r >> 14;
                    const int k = kb * 64 + kc;
                    const float v = (which ? W2 : W1)[(size_t)k * HID + n] * WSCALE;
                    if (which) g_W2s[r] = __float2half_rn(v);
                    else       g_W1s[r] = __float2half_rn(v);
                }
            }
        }
    }
}

// ================= main fused kernel =================
extern "C" __global__ void __launch_bounds__(THREADS, 1)
nerd_fused_kernel(const float* __restrict__ W0f, const float* __restrict__ b0,
                  const float* __restrict__ b1, const float* __restrict__ b2,
                  const float* __restrict__ W3, const float* __restrict__ b3,
                  float* __restrict__ out)
{
    extern __shared__ __half smem[];
    __half* smH = smem;                              // [128][264]
    const unsigned sbase = (unsigned)__cvta_generic_to_shared(smem);

    const int tid  = threadIdx.x;
    const int lane = tid & 31, warp = tid >> 5;      // 8 warps
    const int wm = warp >> 2, wn = warp & 3;         // 2 x 4 grid, tile 64x64
    const int lr = lane >> 2, lc = lane & 3;
    const int l15 = lane & 15, lhi = lane >> 4;
    const int bx = blockIdx.x, bimg = bx >> 7, hrow = bx & 127;

    float acc[128];
#pragma unroll
    for (int i = 0; i < 128; ++i) acc[i] = 0.f;

    // ---- precomputed per-thread constants (bytes) ----
    unsigned aRow[4], bRow[4];
#pragma unroll
    for (int mt = 0; mt < 4; ++mt)
        aRow[mt] = ((wm * 64 + mt * 16 + l15) * SMA_H + lhi * 8) * 2;
#pragma unroll
    for (int np = 0; np < 4; ++np)
        bRow[np] = ((wn * 64 + np * 16 + l15) * SMB_H + lhi * 8) * 2;
    const unsigned Bbuf0 = sbase + OFF_B(0) * 2;     // buffers are SMB_HALF*2 apart
    const unsigned aBuf0 = sbase;                    // A buffers SMA_HALF*2 apart
    // staging thread constants
    const unsigned stB_d = ((tid >> 3) * SMB_H + (tid & 7) * 8) * 2;  // chunk 0; +32 rows per pass
    const unsigned stA_d = ((tid >> 3) * SMA_H + (tid & 7) * 8) * 2;

    // ---- staging (address math once per slab) ----
    auto stage_B = [&](const __half* src, unsigned bufB) {
        unsigned d = bufB + stB_d;
        const __half* sp = src + (size_t)tid * 8;
#pragma unroll
        for (int l = 0; l < 8; ++l) {
            cpa16(d, sp);
            d += 32 * SMB_H * 2;                     // +32 n-rows
            sp += 2048;                              // +256 chunks * 8 halves
        }
    };
    auto stage_A = [&](const __half* src, unsigned bufB) {
        unsigned d = bufB + stA_d;
        const __half* sp = src + (size_t)tid * 8;
#pragma unroll
        for (int l = 0; l < 5; ++l) {
            if (tid + l * 256 < 1056) {
                cpa16(d, sp);
                d += 32 * SMA_H * 2;
                sp += 2048;
            }
        }
    };

    // ---- prologue ----
    const __half* xiBase = g_xiA + ((size_t)(bimg * 2) * 132 + hrow) * (132 * 64);
    // g = ph*2+ch: A source = xiBase + ch*132*8448... layout [((b*2+ch)*132+hp)]
    auto aSrc = [&](int g) {
        const int ph = g >> 1, ch = g & 1;
        return g_xiA + ((size_t)((bimg * 2 + ch) * 132 + hrow + ph)) * (132 * 64);
    };
    auto bSrc0 = [&](int g, int pw) {
        const int ph = g >> 1, ch = g & 1;
        return g_W0s + ((size_t)((ph * 5 + pw) * 2 + ch)) * 16384;
    };

    stage_A(aSrc(0), aBuf0); stage_B(bSrc0(0, 0), Bbuf0); CP_COMMIT;
    stage_B(bSrc0(0, 1), Bbuf0 + SMB_HALF * 2); CP_COMMIT;

    unsigned af[2][4][4], bf[2][4][4];

    // ================= Layer 0: 50 K=64 slabs ================================
    int cur3 = 0, nxt3 = 2;                          // s%3, (s+2)%3
    for (int g = 0; g < 10; ++g) {
        const unsigned aBufB = aBuf0 + (g & 1) * (SMA_HALF * 2);
#pragma unroll 1
        for (int pw = 0; pw < 5; ++pw) {
            const int s = g * 5 + pw;
            CP_WAIT(1);
            __syncthreads();
            if (s + 2 < 50) {
                const int s2 = s + 2;
                const int g2 = (pw < 3) ? g : (pw == 3 ? (g * 5 + 8) / 5 : g + 1);
                // simpler: recompute g2, pw2 from s2 (once per slab; cheap)
                const int gg2 = s2 / 5, pw2 = s2 - gg2 * 5;
                (void)g2;
                stage_B(bSrc0(gg2, pw2), Bbuf0 + nxt3 * (SMB_HALF * 2));
            }
            if (pw == 3 && g + 1 < 10) stage_A(aSrc(g + 1), aBuf0 + ((g + 1) & 1) * (SMA_HALF * 2));
            CP_COMMIT;

            // per-slab base addresses (8 IADDs)
            unsigned aAd[4], bAd[4];
            const unsigned aPw = aBufB + pw * (SMA_H * 2);
            const unsigned bBufB = Bbuf0 + cur3 * (SMB_HALF * 2);
#pragma unroll
            for (int mt = 0; mt < 4; ++mt) aAd[mt] = aPw + aRow[mt];
#pragma unroll
            for (int np = 0; np < 4; ++np) bAd[np] = bBufB + bRow[np];

#define LD_FR(kk_, buf_) do {                                                  \
        _Pragma("unroll") for (int mt = 0; mt < 4; ++mt)                       \
            ldsm4(af[buf_][mt][0], af[buf_][mt][1], af[buf_][mt][2],           \
                  af[buf_][mt][3], aAd[mt] + (kk_) * 32);                      \
        _Pragma("unroll") for (int np = 0; np < 4; ++np)                       \
            ldsm4(bf[buf_][np][0], bf[buf_][np][1], bf[buf_][np][2],           \
                  bf[buf_][np][3], bAd[np] + (kk_) * 32);                      \
        } while (0)

            LD_FR(0, 0);
#pragma unroll
            for (int kk = 0; kk < 4; ++kk) {
                if (kk < 3) {
                    if ((kk & 1) == 0) LD_FR(kk + 1, 1);
                    else               LD_FR(kk + 1, 0);
                }
                const int cur = kk & 1;
#pragma unroll
                for (int np = 0; np < 4; ++np)
#pragma unroll
                    for (int mt = 0; mt < 4; ++mt) {
                        mma16(&acc[(mt * 8 + 2 * np) * 4],     af[cur][mt], bf[cur][np][0], bf[cur][np][2]);
                        mma16(&acc[(mt * 8 + 2 * np + 1) * 4], af[cur][mt], bf[cur][np][1], bf[cur][np][3]);
                    }
            }
#undef LD_FR
            cur3 = (cur3 == 2) ? 0 : cur3 + 1;
            nxt3 = (nxt3 == 2) ? 0 : nxt3 + 1;
        }
    }
    CP_WAIT(0);
    __syncthreads();

    // ---- layer-0 epilogue ----
    {
        const float gy = -1.f + 2.f * (float)hrow * (1.f / 127.f);
#pragma unroll
        for (int mt = 0; mt < 4; ++mt)
#pragma unroll
            for (int nt = 0; nt < 8; ++nt)
#pragma unroll
                for (int hf = 0; hf < 2; ++hf) {
                    const int m = wm * 64 + mt * 16 + lr + hf * 8;
                    const int n0 = wn * 64 + nt * 8 + lc * 2;
                    const float gx = -1.f + 2.f * (float)m * (1.f / 127.f);
                    const float z0 = acc[(mt * 8 + nt) * 4 + hf * 2 + 0] * INV_WSCALE
                                   + gx * W0f[3200 * HID + n0] + gy * W0f[3201 * HID + n0] + b0[n0];
                    const float z1 = acc[(mt * 8 + nt) * 4 + hf * 2 + 1] * INV_WSCALE
                                   + gx * W0f[3200 * HID + n0 + 1] + gy * W0f[3201 * HID + n0 + 1] + b0[n0 + 1];
                    *(__half2*)(smH + m * SMH_H + n0) =
                        __floats2half2_rn(__sinf(OMEGA * z0), __sinf(OMEGA * z1));
                }
    }
    __syncthreads();

    // ================= Layers 1 and 2: 4 K=64 slabs each =====================
    unsigned aRowH[4];
#pragma unroll
    for (int mt = 0; mt < 4; ++mt)
        aRowH[mt] = sbase + ((wm * 64 + mt * 16 + l15) * SMH_H + lhi * 8) * 2;

    for (int L = 0; L < 2; ++L) {
        const __half* Ws = L ? g_W2s : g_W1s;
        const float* bl = L ? b2 : b1;
#pragma unroll
        for (int i = 0; i < 128; ++i) acc[i] = 0.f;

        stage_B(Ws, Bbuf0); CP_COMMIT;
        stage_B(Ws + 16384, Bbuf0 + SMB_HALF * 2); CP_COMMIT;

        cur3 = 0; nxt3 = 2;
#pragma unroll 1
        for (int kb = 0; kb < 4; ++kb) {
            CP_WAIT(1);
            __syncthreads();
            if (kb + 2 < 4) stage_B(Ws + (size_t)(kb + 2) * 16384, Bbuf0 + nxt3 * (SMB_HALF * 2));
            CP_COMMIT;

            unsigned aAd[4], bAd[4];
            const unsigned bBufB = Bbuf0 + cur3 * (SMB_HALF * 2);
#pragma unroll
            for (int mt = 0; mt < 4; ++mt) aAd[mt] = aRowH[mt] + kb * 128;  // 64 halves
#pragma unroll
            for (int np = 0; np < 4; ++np) bAd[np] = bBufB + bRow[np];

#define LD_FR(kk_, buf_) do {                                                  \
        _Pragma("unroll") for (int mt = 0; mt < 4; ++mt)                       \
            ldsm4(af[buf_][mt][0], af[buf_][mt][1], af[buf_][mt][2],           \
                  af[buf_][mt][3], aAd[mt] + (kk_) * 32);                      \
        _Pragma("unroll") for (int np = 0; np < 4; ++np)                       \
            ldsm4(bf[buf_][np][0], bf[buf_][np][1], bf[buf_][np][2],           \
                  bf[buf_][np][3], bAd[np] + (kk_) * 32);                      \
        } while (0)

            LD_FR(0, 0);
#pragma unroll
            for (int kk = 0; kk < 4; ++kk) {
                if (kk < 3) {
                    if ((kk & 1) == 0) LD_FR(kk + 1, 1);
                    else               LD_FR(kk + 1, 0);
                }
                const int cur = kk & 1;
#pragma unroll
                for (int np = 0; np < 4; ++np)
#pragma unroll
                    for (int mt = 0; mt < 4; ++mt) {
                        mma16(&acc[(mt * 8 + 2 * np) * 4],     af[cur][mt], bf[cur][np][0], bf[cur][np][2]);
                        mma16(&acc[(mt * 8 + 2 * np + 1) * 4], af[cur][mt], bf[cur][np][1], bf[cur][np][3]);
                    }
            }
#undef LD_FR
            cur3 = (cur3 == 2) ? 0 : cur3 + 1;
            nxt3 = (nxt3 == 2) ? 0 : nxt3 + 1;
        }
        CP_WAIT(0);
        __syncthreads();

#pragma unroll
        for (int mt = 0; mt < 4; ++mt)
#pragma unroll
            for (int nt = 0; nt < 8; ++nt)
#pragma unroll
                for (int hf = 0; hf < 2; ++hf) {
                    const int m = wm * 64 + mt * 16 + lr + hf * 8;
                    const int n0 = wn * 64 + nt * 8 + lc * 2;
                    const float z0 = acc[(mt * 8 + nt) * 4 + hf * 2 + 0] * INV_WSCALE + bl[n0];
                    const float z1 = acc[(mt * 8 + nt) * 4 + hf * 2 + 1] * INV_WSCALE + bl[n0 + 1];
                    *(__half2*)(smH + m * SMH_H + n0) =
                        __floats2half2_rn(__sinf(OMEGA * z0), __sinf(OMEGA * z1));
                }
        __syncthreads();
    }

    // ================= Head =================
    for (int idx = tid; idx < IMW * OUTC; idx += THREADS) {
        const int p = idx & 127, o = idx >> 7;
        float sum = b3[o];
#pragma unroll 4
        for (int k = 0; k < HID; k += 2) {
            const float2 f = __half22float2(*(const __half2*)(smH + p * SMH_H + k));
            sum += f.x * W3[k * OUTC + o] + f.y * W3[(k + 1) * OUTC + o];
        }
        out[(((size_t)bimg * OUTC + o) * IMH + hrow) * IMW + p] = sum;
    }
}

extern "C" void kernel_launch(void* const* d_in, const int* in_sizes, int n_in,
                              void* d_out, int out_size)
{
    const float* xi = (const float*)d_in[0];
    const float* W0 = (const float*)d_in[1];
    const float* b0 = (const float*)d_in[2];
    const float* W1 = (const float*)d_in[3];
    const float* b1 = (const float*)d_in[4];
    const float* W2 = (const float*)d_in[5];
    const float* b2 = (const float*)d_in[6];
    const float* W3 = (const float*)d_in[7];
    const float* b3 = (const float*)d_in[8];
    float* out = (float*)d_out;

    cudaFuncSetAttribute(nerd_fused_kernel,
                         cudaFuncAttributeMaxDynamicSharedMemorySize, SMEM_BYTES);

    prep_kernel<<<XI_BLOCKS + 464, THREADS>>>(xi, W0, W1, W2);
    nerd_fused_kernel<<<256, THREADS, SMEM_BYTES>>>(W0, b0, b1, b2, W3, b3, out);
}